// round 1
// baseline (speedup 1.0000x reference)
#include <cuda_runtime.h>

#define B_N   8
#define H_IN  384
#define W_IN  384
#define HO    382
#define WO    382
#define KST   64
#define NB    9
#define HOWO  (HO * WO)

// ---- packed f32x2 helpers (Blackwell) ----
__device__ __forceinline__ unsigned long long dup2(float v) {
    unsigned long long r;
    asm("mov.b64 %0, {%1, %1};" : "=l"(r) : "f"(v));
    return r;
}
__device__ __forceinline__ unsigned long long fma2(unsigned long long a,
                                                   unsigned long long b,
                                                   unsigned long long c) {
    unsigned long long d;
    asm("fma.rn.f32x2 %0, %1, %2, %3;" : "=l"(d) : "l"(a), "l"(b), "l"(c));
    return d;
}
__device__ __forceinline__ unsigned long long mul2(unsigned long long a,
                                                   unsigned long long b) {
    unsigned long long d;
    asm("mul.rn.f32x2 %0, %1, %2;" : "=l"(d) : "l"(a), "l"(b));
    return d;
}
__device__ __forceinline__ unsigned long long add2(unsigned long long a,
                                                   unsigned long long b) {
    unsigned long long d;
    asm("add.rn.f32x2 %0, %1, %2;" : "=l"(d) : "l"(a), "l"(b));
    return d;
}
__device__ __forceinline__ void unpack2(unsigned long long d, float& lo, float& hi) {
    asm("mov.b64 {%0, %1}, %2;" : "=f"(lo), "=f"(hi) : "l"(d));
}

// Block: (96, 4) = 384 threads. Each thread computes 4 consecutive output
// columns (j0..j0+3) of one output row. Grid: (ceil(382/4)=96 row-groups, 8 batches).
//
// Shared layout sW: per state-pair sp (32 pairs):
//   [sp*20 + 0..1]  = (b[2sp], b[2sp+1])
//   [sp*20 + 2+2k..3+2k] = (W[k][2sp], W[k][2sp+1])   k = 0..8
// All inner-loop shared loads are uniform addresses -> LDS.64 broadcast, no conflicts.
__global__ __launch_bounds__(384) void qconv_kernel(
    const float* __restrict__ x, const float* __restrict__ W,
    const float* __restrict__ b, const int* __restrict__ keys,
    float* __restrict__ out)
{
    __shared__ float sW[32 * 20];        // 2560 B
    __shared__ float sKeys[KST * NB];    // 2304 B

    const float c0 = 1.5707963267948966f; // pi/2

    const int tid = threadIdx.y * 96 + threadIdx.x;

    // Stage weight pairs + b pairs into shared (one thread per state s).
    if (tid < KST) {
        const int s = tid;
        const int sp = s >> 1, h = s & 1;
        sW[sp * 20 + h] = b[s];
        #pragma unroll
        for (int k = 0; k < NB; ++k)
            sW[sp * 20 + 2 + 2 * k + h] = W[k * KST + s];
    }
    // Stage keys as float.
    for (int idx = tid; idx < KST * NB; idx += 384)
        sKeys[idx] = (float)keys[idx];
    __syncthreads();

    const int bz = blockIdx.y;
    const int i  = blockIdx.x * 4 + threadIdx.y;
    if (i >= HO) return;
    const int j0 = threadIdx.x * 4;

    const float* xb = x + (size_t)bz * (H_IN * W_IN);

    // Load 3x6 patch block (covers the 4 pixels' 3x3 patches), apply the
    // input transform exactly as the reference does, and duplicate into
    // packed f32x2 registers (same value in both lanes: the two lanes are
    // two adjacent Fock states sharing the patch value).
    unsigned long long P[18];
    #pragma unroll
    for (int r = 0; r < 3; ++r) {
        #pragma unroll
        for (int c = 0; c < 6; ++c) {
            int col = j0 + c;
            col = (col < W_IN) ? col : (W_IN - 1);   // clamp (values unused at edge)
            float v = (__ldg(&xb[(i + r) * W_IN + col]) - 0.5f) * c0;
            P[r * 6 + c] = dup2(v);
        }
    }

    float best0 = -3.4e38f, best1 = -3.4e38f, best2 = -3.4e38f, best3 = -3.4e38f;
    int   bi0 = 0, bi1 = 0, bi2 = 0, bi3 = 0;

    #pragma unroll 4
    for (int sp = 0; sp < 32; ++sp) {
        const unsigned long long* wb =
            reinterpret_cast<const unsigned long long*>(&sW[sp * 20]);
        const unsigned long long bb = wb[0];

        // k = 0 initializes via mul (dot product starts at p0*w0, matching a
        // left-to-right fp32 reduction; b added at the end like the reference).
        unsigned long long w0 = wb[1];
        unsigned long long a0 = mul2(P[0], w0);
        unsigned long long a1 = mul2(P[1], w0);
        unsigned long long a2 = mul2(P[2], w0);
        unsigned long long a3 = mul2(P[3], w0);
        #pragma unroll
        for (int k = 1; k < NB; ++k) {
            const unsigned long long wk = wb[1 + k];
            const int dy = k / 3, dx = k % 3;
            a0 = fma2(P[dy * 6 + dx + 0], wk, a0);
            a1 = fma2(P[dy * 6 + dx + 1], wk, a1);
            a2 = fma2(P[dy * 6 + dx + 2], wk, a2);
            a3 = fma2(P[dy * 6 + dx + 3], wk, a3);
        }
        a0 = add2(a0, bb);
        a1 = add2(a1, bb);
        a2 = add2(a2, bb);
        a3 = add2(a3, bb);

        const int s0 = sp * 2;
        float lo, hi;
        unpack2(a0, lo, hi);
        if (lo > best0) { best0 = lo; bi0 = s0; }
        if (hi > best0) { best0 = hi; bi0 = s0 + 1; }
        unpack2(a1, lo, hi);
        if (lo > best1) { best1 = lo; bi1 = s0; }
        if (hi > best1) { best1 = hi; bi1 = s0 + 1; }
        unpack2(a2, lo, hi);
        if (lo > best2) { best2 = lo; bi2 = s0; }
        if (hi > best2) { best2 = hi; bi2 = s0 + 1; }
        unpack2(a3, lo, hi);
        if (lo > best3) { best3 = lo; bi3 = s0; }
        if (hi > best3) { best3 = hi; bi3 = s0 + 1; }
    }

    // Decode + store: gather the winning key row per pixel.
    float* ob = out + (size_t)bz * (NB * HOWO) + (size_t)i * WO + j0;
    const int bis[4] = { bi0, bi1, bi2, bi3 };
    #pragma unroll
    for (int p = 0; p < 4; ++p) {
        if (j0 + p < WO) {
            const float* kr = &sKeys[bis[p] * NB];
            #pragma unroll
            for (int k = 0; k < NB; ++k)
                ob[(size_t)k * HOWO + p] = kr[k];
        }
    }
}

extern "C" void kernel_launch(void* const* d_in, const int* in_sizes, int n_in,
                              void* d_out, int out_size) {
    const float* x    = (const float*)d_in[0];
    const float* W    = (const float*)d_in[1];
    const float* b    = (const float*)d_in[2];
    const int*   keys = (const int*)d_in[3];
    float*       out  = (float*)d_out;

    dim3 block(96, 4);            // 384 threads, 3 warps per output row
    dim3 grid((HO + 3) / 4, B_N); // (96, 8)
    qconv_kernel<<<grid, block>>>(x, W, b, keys, out);
}

// round 2
// speedup vs baseline: 1.2091x; 1.2091x over previous
#include <cuda_runtime.h>

#define B_N   8
#define H_IN  384
#define W_IN  384
#define HO    382
#define WO    382
#define KST   64
#define NB    9
#define HOWO  (HO * WO)

// ---- packed f32x2 helpers (Blackwell) ----
__device__ __forceinline__ unsigned long long dup2(float v) {
    unsigned long long r;
    asm("mov.b64 %0, {%1, %1};" : "=l"(r) : "f"(v));
    return r;
}
__device__ __forceinline__ unsigned long long fma2(unsigned long long a,
                                                   unsigned long long b,
                                                   unsigned long long c) {
    unsigned long long d;
    asm("fma.rn.f32x2 %0, %1, %2, %3;" : "=l"(d) : "l"(a), "l"(b), "l"(c));
    return d;
}
__device__ __forceinline__ unsigned long long mul2(unsigned long long a,
                                                   unsigned long long b) {
    unsigned long long d;
    asm("mul.rn.f32x2 %0, %1, %2;" : "=l"(d) : "l"(a), "l"(b));
    return d;
}
__device__ __forceinline__ unsigned long long add2(unsigned long long a,
                                                   unsigned long long b) {
    unsigned long long d;
    asm("add.rn.f32x2 %0, %1, %2;" : "=l"(d) : "l"(a), "l"(b));
    return d;
}
__device__ __forceinline__ void unpack2(unsigned long long d, float& lo, float& hi) {
    asm("mov.b64 {%0, %1}, %2;" : "=f"(lo), "=f"(hi) : "l"(d));
}

// Block: (96, 4) = 384 threads. Thread = 4 consecutive output columns of one
// output row. Grid: (96 row-groups, 8 batches).
//
// Shared layout sW: per state-pair sp (32 pairs), stride 24 floats (96 B,
// 16B-aligned -> LDS.128):
//   [sp*24 + 0..1]        = (b[2sp], b[2sp+1])
//   [sp*24 + 2+2k..3+2k]  = (W[k][2sp], W[k][2sp+1])   k = 0..8
//   [sp*24 + 20..23]      = pad
// All inner-loop shared loads are warp-uniform -> LDS.128 broadcast.
__global__ __launch_bounds__(384) void qconv_kernel(
    const float* __restrict__ x, const float* __restrict__ W,
    const float* __restrict__ b, const int* __restrict__ keys,
    float* __restrict__ out)
{
    __shared__ __align__(16) float sW[32 * 24];   // 3072 B
    __shared__ float sKeys[KST * NB];             // 2304 B

    const float c0 = 1.5707963267948966f; // pi/2

    const int tid = threadIdx.y * 96 + threadIdx.x;

    // Stage weight pairs + b pairs into shared (one thread per state s).
    if (tid < KST) {
        const int s = tid;
        const int sp = s >> 1, h = s & 1;
        sW[sp * 24 + h] = b[s];
        #pragma unroll
        for (int k = 0; k < NB; ++k)
            sW[sp * 24 + 2 + 2 * k + h] = W[k * KST + s];
    }
    // Stage keys as float.
    for (int idx = tid; idx < KST * NB; idx += 384)
        sKeys[idx] = (float)keys[idx];
    __syncthreads();

    const int bz = blockIdx.y;
    const int i  = blockIdx.x * 4 + threadIdx.y;
    if (i >= HO) return;
    const int j0 = threadIdx.x * 4;       // j0 <= 380, always a multiple of 4

    const float* xb = x + (size_t)bz * (H_IN * W_IN);

    // Load 3x6 patch block with vector loads (float4 + predicated float2),
    // apply the input transform exactly as the reference ((x-0.5)*pi/2,
    // sub-then-mul -> not FMA-contractible), duplicate into packed f32x2.
    unsigned long long P[18];
    const bool tail_ok = (j0 <= W_IN - 6);   // j0+5 <= 383
    #pragma unroll
    for (int r = 0; r < 3; ++r) {
        const float* rp = xb + (size_t)(i + r) * W_IN + j0;
        float4 v4 = *reinterpret_cast<const float4*>(rp);
        float2 v2 = tail_ok ? *reinterpret_cast<const float2*>(rp + 4)
                            : make_float2(0.f, 0.f);
        float v[6] = { v4.x, v4.y, v4.z, v4.w, v2.x, v2.y };
        #pragma unroll
        for (int c = 0; c < 6; ++c)
            P[r * 6 + c] = dup2((v[c] - 0.5f) * c0);
    }

    float best0 = -3.4e38f, best1 = -3.4e38f, best2 = -3.4e38f, best3 = -3.4e38f;
    int   bi0 = 0, bi1 = 0, bi2 = 0, bi3 = 0;

    #pragma unroll 8
    for (int sp = 0; sp < 32; ++sp) {
        const ulonglong2* wp =
            reinterpret_cast<const ulonglong2*>(&sW[sp * 24]);
        const ulonglong2 q0 = wp[0];   // (b_pair, w0)
        const ulonglong2 q1 = wp[1];   // (w1, w2)
        const ulonglong2 q2 = wp[2];   // (w3, w4)
        const ulonglong2 q3 = wp[3];   // (w5, w6)
        const ulonglong2 q4 = wp[4];   // (w7, w8)

        // Exact same summation order as the passing R1 kernel:
        // (((p0*w0 + p1*w1) + ... + p8*w8) + b)
        unsigned long long a0 = mul2(P[0], q0.y);
        unsigned long long a1 = mul2(P[1], q0.y);
        unsigned long long a2 = mul2(P[2], q0.y);
        unsigned long long a3 = mul2(P[3], q0.y);

        a0 = fma2(P[1],  q1.x, a0);  a1 = fma2(P[2],  q1.x, a1);
        a2 = fma2(P[3],  q1.x, a2);  a3 = fma2(P[4],  q1.x, a3);

        a0 = fma2(P[2],  q1.y, a0);  a1 = fma2(P[3],  q1.y, a1);
        a2 = fma2(P[4],  q1.y, a2);  a3 = fma2(P[5],  q1.y, a3);

        a0 = fma2(P[6],  q2.x, a0);  a1 = fma2(P[7],  q2.x, a1);
        a2 = fma2(P[8],  q2.x, a2);  a3 = fma2(P[9],  q2.x, a3);

        a0 = fma2(P[7],  q2.y, a0);  a1 = fma2(P[8],  q2.y, a1);
        a2 = fma2(P[9],  q2.y, a2);  a3 = fma2(P[10], q2.y, a3);

        a0 = fma2(P[8],  q3.x, a0);  a1 = fma2(P[9],  q3.x, a1);
        a2 = fma2(P[10], q3.x, a2);  a3 = fma2(P[11], q3.x, a3);

        a0 = fma2(P[12], q3.y, a0);  a1 = fma2(P[13], q3.y, a1);
        a2 = fma2(P[14], q3.y, a2);  a3 = fma2(P[15], q3.y, a3);

        a0 = fma2(P[13], q4.x, a0);  a1 = fma2(P[14], q4.x, a1);
        a2 = fma2(P[15], q4.x, a2);  a3 = fma2(P[16], q4.x, a3);

        a0 = fma2(P[14], q4.y, a0);  a1 = fma2(P[15], q4.y, a1);
        a2 = fma2(P[16], q4.y, a2);  a3 = fma2(P[17], q4.y, a3);

        a0 = add2(a0, q0.x);
        a1 = add2(a1, q0.x);
        a2 = add2(a2, q0.x);
        a3 = add2(a3, q0.x);

        const int s0 = sp * 2;
        float lo, hi;
        unpack2(a0, lo, hi);
        if (lo > best0) { best0 = lo; bi0 = s0; }
        if (hi > best0) { best0 = hi; bi0 = s0 + 1; }
        unpack2(a1, lo, hi);
        if (lo > best1) { best1 = lo; bi1 = s0; }
        if (hi > best1) { best1 = hi; bi1 = s0 + 1; }
        unpack2(a2, lo, hi);
        if (lo > best2) { best2 = lo; bi2 = s0; }
        if (hi > best2) { best2 = hi; bi2 = s0 + 1; }
        unpack2(a3, lo, hi);
        if (lo > best3) { best3 = lo; bi3 = s0; }
        if (hi > best3) { best3 = hi; bi3 = s0 + 1; }
    }

    // Decode + store with float2 stores (8B-aligned: j0 even, WO even).
    // Pixels j0, j0+1 always valid (j0 <= 380). Pixels j0+2, j0+3 valid
    // iff j0 <= 378 (WO = 382 = 4*95 + 2).
    float* ob = out + (size_t)bz * (NB * HOWO) + (size_t)i * WO + j0;
    const float* kr0 = &sKeys[bi0 * NB];
    const float* kr1 = &sKeys[bi1 * NB];
    const float* kr2 = &sKeys[bi2 * NB];
    const float* kr3 = &sKeys[bi3 * NB];
    const bool hi_ok = (j0 + 3 < WO);
    #pragma unroll
    for (int k = 0; k < NB; ++k) {
        float* op = ob + (size_t)k * HOWO;
        *reinterpret_cast<float2*>(op) = make_float2(kr0[k], kr1[k]);
        if (hi_ok)
            *reinterpret_cast<float2*>(op + 2) = make_float2(kr2[k], kr3[k]);
    }
}

extern "C" void kernel_launch(void* const* d_in, const int* in_sizes, int n_in,
                              void* d_out, int out_size) {
    const float* x    = (const float*)d_in[0];
    const float* W    = (const float*)d_in[1];
    const float* b    = (const float*)d_in[2];
    const int*   keys = (const int*)d_in[3];
    float*       out  = (float*)d_out;

    dim3 block(96, 4);            // 384 threads
    dim3 grid((HO + 3) / 4, B_N); // (96, 8)
    qconv_kernel<<<grid, block>>>(x, W, b, keys, out);
}

// round 3
// speedup vs baseline: 1.2580x; 1.0404x over previous
#include <cuda_runtime.h>

#define B_N   8
#define H_IN  384
#define W_IN  384
#define HO    382
#define WO    382
#define KST   64
#define NB    9
#define HOWO  (HO * WO)

// ---- packed f32x2 helpers (Blackwell) ----
__device__ __forceinline__ unsigned long long dup2(float v) {
    unsigned long long r;
    asm("mov.b64 %0, {%1, %1};" : "=l"(r) : "f"(v));
    return r;
}
__device__ __forceinline__ unsigned long long fma2(unsigned long long a,
                                                   unsigned long long b,
                                                   unsigned long long c) {
    unsigned long long d;
    asm("fma.rn.f32x2 %0, %1, %2, %3;" : "=l"(d) : "l"(a), "l"(b), "l"(c));
    return d;
}
__device__ __forceinline__ unsigned long long mul2(unsigned long long a,
                                                   unsigned long long b) {
    unsigned long long d;
    asm("mul.rn.f32x2 %0, %1, %2;" : "=l"(d) : "l"(a), "l"(b));
    return d;
}
__device__ __forceinline__ unsigned long long add2(unsigned long long a,
                                                   unsigned long long b) {
    unsigned long long d;
    asm("add.rn.f32x2 %0, %1, %2;" : "=l"(d) : "l"(a), "l"(b));
    return d;
}
__device__ __forceinline__ void unpack2(unsigned long long d, float& lo, float& hi) {
    asm("mov.b64 {%0, %1}, %2;" : "=f"(lo), "=f"(hi) : "l"(d));
}

// Block: (96, 4) = 384 threads. Thread = 4 consecutive output columns of one
// output row. Grid: (96 row-groups, 8 batches).
//
// Shared layout sW: per state-pair sp (32 pairs), stride 24 floats (96 B,
// 16B-aligned -> LDS.128):
//   [sp*24 + 0..1]        = (b[2sp], b[2sp+1])
//   [sp*24 + 2+2k..3+2k]  = (W[k][2sp], W[k][2sp+1])   k = 0..8
__global__ __launch_bounds__(384) void qconv_kernel(
    const float* __restrict__ x, const float* __restrict__ W,
    const float* __restrict__ b, const int* __restrict__ keys,
    float* __restrict__ out)
{
    __shared__ __align__(16) float sW[32 * 24];   // 3072 B
    __shared__ float sKeys[KST * NB];             // 2304 B

    const float c0 = 1.5707963267948966f; // pi/2

    const int tid = threadIdx.y * 96 + threadIdx.x;

    if (tid < KST) {
        const int s = tid;
        const int sp = s >> 1, h = s & 1;
        sW[sp * 24 + h] = b[s];
        #pragma unroll
        for (int k = 0; k < NB; ++k)
            sW[sp * 24 + 2 + 2 * k + h] = W[k * KST + s];
    }
    for (int idx = tid; idx < KST * NB; idx += 384)
        sKeys[idx] = (float)keys[idx];
    __syncthreads();

    const int bz = blockIdx.y;
    const int i  = blockIdx.x * 4 + threadIdx.y;
    if (i >= HO) return;
    const int j0 = threadIdx.x * 4;       // multiple of 4, <= 380

    const float* xb = x + bz * (H_IN * W_IN);

    // 3x6 patch block: float4 + predicated float2 per row; transform
    // (v - 0.5f) * pi/2 exactly as before; duplicate into f32x2 lanes.
    unsigned long long P[18];
    const bool tail_ok = (j0 <= W_IN - 6);
    #pragma unroll
    for (int r = 0; r < 3; ++r) {
        const float* rp = xb + (i + r) * W_IN + j0;
        float4 v4 = *reinterpret_cast<const float4*>(rp);
        float2 v2 = tail_ok ? *reinterpret_cast<const float2*>(rp + 4)
                            : make_float2(0.f, 0.f);
        float v[6] = { v4.x, v4.y, v4.z, v4.w, v2.x, v2.y };
        #pragma unroll
        for (int c = 0; c < 6; ++c)
            P[r * 6 + c] = dup2((v[c] - 0.5f) * c0);
    }

    float best0 = -3.4e38f, best1 = -3.4e38f, best2 = -3.4e38f, best3 = -3.4e38f;
    int   bi0 = 0, bi1 = 0, bi2 = 0, bi3 = 0;

    #pragma unroll 16
    for (int sp = 0; sp < 32; ++sp) {
        const ulonglong2* wp =
            reinterpret_cast<const ulonglong2*>(&sW[sp * 24]);
        const ulonglong2 q0 = wp[0];   // (b_pair, w0)
        const ulonglong2 q1 = wp[1];   // (w1, w2)
        const ulonglong2 q2 = wp[2];   // (w3, w4)
        const ulonglong2 q3 = wp[3];   // (w5, w6)
        const ulonglong2 q4 = wp[4];   // (w7, w8)

        // Bit-identical summation order: (((p0*w0 + p1*w1) + ... ) + b)
        unsigned long long a0 = mul2(P[0], q0.y);
        unsigned long long a1 = mul2(P[1], q0.y);
        unsigned long long a2 = mul2(P[2], q0.y);
        unsigned long long a3 = mul2(P[3], q0.y);

        a0 = fma2(P[1],  q1.x, a0);  a1 = fma2(P[2],  q1.x, a1);
        a2 = fma2(P[3],  q1.x, a2);  a3 = fma2(P[4],  q1.x, a3);

        a0 = fma2(P[2],  q1.y, a0);  a1 = fma2(P[3],  q1.y, a1);
        a2 = fma2(P[4],  q1.y, a2);  a3 = fma2(P[5],  q1.y, a3);

        a0 = fma2(P[6],  q2.x, a0);  a1 = fma2(P[7],  q2.x, a1);
        a2 = fma2(P[8],  q2.x, a2);  a3 = fma2(P[9],  q2.x, a3);

        a0 = fma2(P[7],  q2.y, a0);  a1 = fma2(P[8],  q2.y, a1);
        a2 = fma2(P[9],  q2.y, a2);  a3 = fma2(P[10], q2.y, a3);

        a0 = fma2(P[8],  q3.x, a0);  a1 = fma2(P[9],  q3.x, a1);
        a2 = fma2(P[10], q3.x, a2);  a3 = fma2(P[11], q3.x, a3);

        a0 = fma2(P[12], q3.y, a0);  a1 = fma2(P[13], q3.y, a1);
        a2 = fma2(P[14], q3.y, a2);  a3 = fma2(P[15], q3.y, a3);

        a0 = fma2(P[13], q4.x, a0);  a1 = fma2(P[14], q4.x, a1);
        a2 = fma2(P[15], q4.x, a2);  a3 = fma2(P[16], q4.x, a3);

        a0 = fma2(P[14], q4.y, a0);  a1 = fma2(P[15], q4.y, a1);
        a2 = fma2(P[16], q4.y, a2);  a3 = fma2(P[17], q4.y, a3);

        a0 = add2(a0, q0.x);
        a1 = add2(a1, q0.x);
        a2 = add2(a2, q0.x);
        a3 = add2(a3, q0.x);

        // Argmax update, restructured to minimize the best-dependent chain.
        // Semantics identical to sequential strict-> scan (lo first, then hi):
        //   pair winner = (hi > lo) ? (hi, s0+1) : (lo, s0)
        //   update iff winner > best
        const int s0 = sp * 2;
        float lo, hi;
        {
            unpack2(a0, lo, hi);
            const bool q = hi > lo;
            const float cand = q ? hi : lo;
            const int   ci   = q ? s0 + 1 : s0;
            if (cand > best0) { best0 = cand; bi0 = ci; }
        }
        {
            unpack2(a1, lo, hi);
            const bool q = hi > lo;
            const float cand = q ? hi : lo;
            const int   ci   = q ? s0 + 1 : s0;
            if (cand > best1) { best1 = cand; bi1 = ci; }
        }
        {
            unpack2(a2, lo, hi);
            const bool q = hi > lo;
            const float cand = q ? hi : lo;
            const int   ci   = q ? s0 + 1 : s0;
            if (cand > best2) { best2 = cand; bi2 = ci; }
        }
        {
            unpack2(a3, lo, hi);
            const bool q = hi > lo;
            const float cand = q ? hi : lo;
            const int   ci   = q ? s0 + 1 : s0;
            if (cand > best3) { best3 = cand; bi3 = ci; }
        }
    }

    // Decode + store (int32 addressing; float2 stores, 8B-aligned).
    const int obase = bz * (NB * HOWO) + i * WO + j0;
    const float* kr0 = &sKeys[bi0 * NB];
    const float* kr1 = &sKeys[bi1 * NB];
    const float* kr2 = &sKeys[bi2 * NB];
    const float* kr3 = &sKeys[bi3 * NB];
    const bool hi_ok = (j0 + 3 < WO);
    #pragma unroll
    for (int k = 0; k < NB; ++k) {
        float* op = out + obase + k * HOWO;
        *reinterpret_cast<float2*>(op) = make_float2(kr0[k], kr1[k]);
        if (hi_ok)
            *reinterpret_cast<float2*>(op + 2) = make_float2(kr2[k], kr3[k]);
    }
}

extern "C" void kernel_launch(void* const* d_in, const int* in_sizes, int n_in,
                              void* d_out, int out_size) {
    const float* x    = (const float*)d_in[0];
    const float* W    = (const float*)d_in[1];
    const float* b    = (const float*)d_in[2];
    const int*   keys = (const int*)d_in[3];
    float*       out  = (float*)d_out;

    dim3 block(96, 4);            // 384 threads
    dim3 grid((HO + 3) / 4, B_N); // (96, 8)
    qconv_kernel<<<grid, block>>>(x, W, b, keys, out);
}